// round 3
// baseline (speedup 1.0000x reference)
#include <cuda_runtime.h>

#define LH 128
#define LP 32
#define DM 64
#define HID 64
#define MAXLEN 128
#define ST 68      // activation/weight-panel row stride (floats)
#define KST 80     // kv row stride
#define HOFF 20    // kv per-head offset (banks disjoint across 4 heads)

typedef unsigned long long u64;

__device__ __forceinline__ u64 pk2(float lo, float hi) {
    u64 r; asm("mov.b64 %0,{%1,%2};" : "=l"(r) : "f"(lo), "f"(hi)); return r;
}
__device__ __forceinline__ void fma2(u64& d, u64 a, u64 b) {
    asm("fma.rn.f32x2 %0,%1,%2,%3;" : "=l"(d) : "l"(a), "l"(b), "l"(d));
}
__device__ __forceinline__ void mul2(u64& d, u64 a, u64 b) {
    asm("mul.rn.f32x2 %0,%1,%2;" : "=l"(d) : "l"(a), "l"(b));
}
__device__ __forceinline__ float2 up2(u64 v) {
    float2 r; asm("mov.b64 {%0,%1},%2;" : "=f"(r.x), "=f"(r.y) : "l"(v)); return r;
}

// smem layout (floats)
#define O_X  0                 // [128][ST] hla -> h1a
#define O_C  (LH*ST)           // [128][ST] pep(rows0..31) -> LN(ctx) -> z
#define O_Q  (2*LH*ST)         // [128][ST] q
#define O_H  (3*LH*ST)         // [128][ST] h1b
#define O_KV (4*LH*ST)         // [32][KST] kv, head-padded
#define O_W0 (O_KV + LP*KST)   // 4 weight panels [64][ST]
#define O_W1 (O_W0 + 64*ST)
#define O_W2 (O_W1 + 64*ST)
#define O_W3 (O_W2 + 64*ST)
#define SMEM_FLOATS (O_W3 + 64*ST)
#define SMEM_BYTES  (SMEM_FLOATS * 4)   // 219136 B

// acc init from bias at cols c..c+3 and c+32..c+35
__device__ __forceinline__ void bias_init(u64 a[4], const float* __restrict__ b, int c) {
    float4 x = __ldg((const float4*)(b + c));
    float4 y = __ldg((const float4*)(b + c + 32));
    a[0] = pk2(x.x, x.y); a[1] = pk2(x.z, x.w);
    a[2] = pk2(y.x, y.y); a[3] = pk2(y.z, y.w);
}

// acc -> smem row m, split cols c / c+32
__device__ __forceinline__ void store_split(float* dst, int m, int c, const u64 a[4]) {
    float2 f0 = up2(a[0]), f1 = up2(a[1]), f2 = up2(a[2]), f3 = up2(a[3]);
    *(float4*)(dst + m * ST + c)      = make_float4(f0.x, f0.y, f1.x, f1.y);
    *(float4*)(dst + m * ST + c + 32) = make_float4(f2.x, f2.y, f3.x, f3.y);
}

__device__ __forceinline__ void gelu4(u64 a[4]) {
    #pragma unroll
    for (int i = 0; i < 4; i++) {
        float2 f = up2(a[i]);
        f.x *= normcdff(f.x);
        f.y *= normcdff(f.y);
        a[i] = pk2(f.x, f.y);
    }
}

// acc += A[m][:64] * W[:64][{c..c+3, c+32..c+35}]
__device__ __forceinline__ void gemm64(const float* __restrict__ sArow,
                                       const float* __restrict__ sW, int c, u64 acc[4]) {
    #pragma unroll 4
    for (int k0 = 0; k0 < 64; k0 += 4) {
        float4 a = *(const float4*)(sArow + k0);
        #pragma unroll
        for (int j = 0; j < 4; j++) {
            const float* wr = sW + (k0 + j) * ST + c;
            ulonglong2 w0 = *(const ulonglong2*)wr;         // cols c..c+3
            ulonglong2 w1 = *(const ulonglong2*)(wr + 32);  // cols c+32..c+35
            float av = (j == 0) ? a.x : (j == 1) ? a.y : (j == 2) ? a.z : a.w;
            u64 d = pk2(av, av);
            fma2(acc[0], d, w0.x);
            fma2(acc[1], d, w0.y);
            fma2(acc[2], d, w1.x);
            fma2(acc[3], d, w1.y);
        }
    }
}

__global__ __launch_bounds__(1024, 1)
void h2p_kernel(const float* __restrict__ hla_in,
                const float* __restrict__ pep_in,
                const float* __restrict__ W_hla, const float* __restrict__ b_hla,
                const float* __restrict__ W_pep, const float* __restrict__ b_pep,
                const float* __restrict__ rel_bias,
                const float* __restrict__ ln_g, const float* __restrict__ ln_b,
                const float* __restrict__ W1, const float* __restrict__ b1,
                const float* __restrict__ W2, const float* __restrict__ b2,
                const float* __restrict__ W_out, const float* __restrict__ b_out,
                float* __restrict__ out)
{
    extern __shared__ float sm[];
    const int t  = threadIdx.x;
    const int bb = blockIdx.x;
    const int m  = t >> 3;          // output row 0..127
    const int c  = (t & 7) * 4;     // col group base 0..28

    const int wk = t >> 4;          // panel-load row (0..63)
    const int wc = (t & 15) * 4;    // panel-load col

    // ---------------- stage inputs + first two panels ----------------
    {
        const float4* hg = (const float4*)(hla_in + (size_t)bb * LH * DM);
        int i0 = t, i1 = t + 1024;
        float4 v0 = hg[i0], v1 = hg[i1];
        *(float4*)&sm[O_X + (i0 >> 4) * ST + (i0 & 15) * 4] = v0;
        *(float4*)&sm[O_X + (i1 >> 4) * ST + (i1 & 15) * 4] = v1;
    }
    if (t < 512) {
        const float4* pg = (const float4*)(pep_in + (size_t)bb * LP * DM);
        float4 v = pg[t];
        *(float4*)&sm[O_C + (t >> 4) * ST + (t & 15) * 4] = v;
    }
    *(float4*)&sm[O_W0 + wk * ST + wc] = __ldg((const float4*)(W_pep + wk * HID + wc));
    *(float4*)&sm[O_W1 + wk * ST + wc] = __ldg((const float4*)(W_hla + wk * HID + wc));
    __syncthreads();   // S0

    // ---------------- kv = pep @ W_pep + b_pep (t<256); pipeline W1a->W2 ----------------
    float4 pre = __ldg((const float4*)(W1 + wk * (2 * HID) + wc));   // W1 cols 0..63
    if (t < 256) {
        u64 a[4];
        bias_init(a, b_pep, c);
        gemm64(&sm[O_C + m * ST], &sm[O_W0], c, a);   // m <= 31 here
        float2 f0 = up2(a[0]), f1 = up2(a[1]), f2 = up2(a[2]), f3 = up2(a[3]);
        int c2 = c + 32;
        *(float4*)&sm[O_KV + m * KST + (c  >> 4) * HOFF + (c  & 15)] =
            make_float4(f0.x, f0.y, f1.x, f1.y);
        *(float4*)&sm[O_KV + m * KST + (c2 >> 4) * HOFF + (c2 & 15)] =
            make_float4(f2.x, f2.y, f3.x, f3.y);
    }
    *(float4*)&sm[O_W2 + wk * ST + wc] = pre;
    __syncthreads();   // S1

    // ---------------- q = hla @ W_hla + b_hla -> Q; pipeline W1b->W0 ----------------
    pre = __ldg((const float4*)(W1 + wk * (2 * HID) + HID + wc));    // W1 cols 64..127
    {
        u64 qa[4];
        bias_init(qa, b_hla, c);
        gemm64(&sm[O_X + m * ST], &sm[O_W1], c, qa);
        store_split(&sm[O_Q], m, c, qa);
    }
    *(float4*)&sm[O_W0 + wk * ST + wc] = pre;
    __syncthreads();   // S2

    // ---------------- attention + LN (t<512); t>=512 loads W2a->W1 ----------------
    if (t < 512) {
        const int r = t >> 2, h = t & 3;
        const float* qrow = &sm[O_Q + r * ST + h * 16];
        ulonglong2 qA = *(const ulonglong2*)(qrow + 0);
        ulonglong2 qB = *(const ulonglong2*)(qrow + 4);
        ulonglong2 qC = *(const ulonglong2*)(qrow + 8);
        ulonglong2 qD = *(const ulonglong2*)(qrow + 12);

        float sc[32];
        const float* brow = rel_bias + h * (MAXLEN * MAXLEN) + r * MAXLEN;
        #pragma unroll
        for (int k4 = 0; k4 < 8; k4++) {
            float4 bv = __ldg((const float4*)&brow[k4 * 4]);
            sc[k4*4+0] = bv.x; sc[k4*4+1] = bv.y; sc[k4*4+2] = bv.z; sc[k4*4+3] = bv.w;
        }
        #pragma unroll
        for (int k = 0; k < LP; k++) {
            const float* kr = &sm[O_KV + k * KST + h * HOFF];
            ulonglong2 v0 = *(const ulonglong2*)(kr + 0);
            ulonglong2 v1 = *(const ulonglong2*)(kr + 4);
            ulonglong2 v2 = *(const ulonglong2*)(kr + 8);
            ulonglong2 v3 = *(const ulonglong2*)(kr + 12);
            u64 s;
            mul2(s, qA.x, v0.x);
            fma2(s, qA.y, v0.y);
            fma2(s, qB.x, v1.x);
            fma2(s, qB.y, v1.y);
            fma2(s, qC.x, v2.x);
            fma2(s, qC.y, v2.y);
            fma2(s, qD.x, v3.x);
            fma2(s, qD.y, v3.y);
            float2 sp = up2(s);
            sc[k] = fmaf(0.25f, sp.x + sp.y, sc[k]);
        }
        float mx = sc[0];
        #pragma unroll
        for (int k = 1; k < LP; k++) mx = fmaxf(mx, sc[k]);
        float ssum = 0.f;
        #pragma unroll
        for (int k = 0; k < LP; k++) { sc[k] = __expf(sc[k] - mx); ssum += sc[k]; }
        float inv = 1.0f / ssum;

        u64 cx[8];
        #pragma unroll
        for (int i = 0; i < 8; i++) cx[i] = 0ull;
        #pragma unroll
        for (int k = 0; k < LP; k++) {
            const float* kr = &sm[O_KV + k * KST + h * HOFF];
            ulonglong2 v0 = *(const ulonglong2*)(kr + 0);
            ulonglong2 v1 = *(const ulonglong2*)(kr + 4);
            ulonglong2 v2 = *(const ulonglong2*)(kr + 8);
            ulonglong2 v3 = *(const ulonglong2*)(kr + 12);
            u64 pd = pk2(sc[k], sc[k]);
            fma2(cx[0], pd, v0.x); fma2(cx[1], pd, v0.y);
            fma2(cx[2], pd, v1.x); fma2(cx[3], pd, v1.y);
            fma2(cx[4], pd, v2.x); fma2(cx[5], pd, v2.y);
            fma2(cx[6], pd, v3.x); fma2(cx[7], pd, v3.y);
        }
        float x[16];
        #pragma unroll
        for (int i = 0; i < 8; i++) {
            float2 f = up2(cx[i]);
            x[2*i]   = f.x * inv;
            x[2*i+1] = f.y * inv;
        }
        // LayerNorm across the 4 head-threads of this row (lanes t, t^1, t^2)
        float s1 = 0.f, s2 = 0.f;
        #pragma unroll
        for (int i = 0; i < 16; i++) { s1 += x[i]; s2 = fmaf(x[i], x[i], s2); }
        s1 += __shfl_xor_sync(0xffffffffu, s1, 1);
        s2 += __shfl_xor_sync(0xffffffffu, s2, 1);
        s1 += __shfl_xor_sync(0xffffffffu, s1, 2);
        s2 += __shfl_xor_sync(0xffffffffu, s2, 2);
        float mu   = s1 * (1.0f / 64.0f);
        float var  = s2 * (1.0f / 64.0f) - mu * mu;
        float rstd = rsqrtf(var + 1e-5f);
        #pragma unroll
        for (int c4 = 0; c4 < 4; c4++) {
            float4 gv = __ldg((const float4*)&ln_g[h * 16 + c4 * 4]);
            float4 bv = __ldg((const float4*)&ln_b[h * 16 + c4 * 4]);
            float4 o;
            o.x = (x[c4*4+0] - mu) * rstd * gv.x + bv.x;
            o.y = (x[c4*4+1] - mu) * rstd * gv.y + bv.y;
            o.z = (x[c4*4+2] - mu) * rstd * gv.z + bv.z;
            o.w = (x[c4*4+3] - mu) * rstd * gv.w + bv.w;
            *(float4*)&sm[O_C + r * ST + h * 16 + c4 * 4] = o;
        }
    } else {
        int i0 = t - 512, i1 = i0 + 512;   // W2 rows 0..63 -> W1 panel
        int k0 = i0 >> 4, c0 = (i0 & 15) * 4;
        int k1 = i1 >> 4, c1 = (i1 & 15) * 4;
        *(float4*)&sm[O_W1 + k0 * ST + c0] = __ldg((const float4*)(W2 + k0 * HID + c0));
        *(float4*)&sm[O_W1 + k1 * ST + c1] = __ldg((const float4*)(W2 + k1 * HID + c1));
    }
    __syncthreads();   // S3

    // ---------------- h1a = gelu(LNctx @ W1a + b1[:64]) -> X; pipeline W2b->W3 ----------------
    pre = __ldg((const float4*)(W2 + 64 * HID + wk * HID + wc));
    {
        u64 ha[4];
        bias_init(ha, b1, c);
        gemm64(&sm[O_C + m * ST], &sm[O_W2], c, ha);
        gelu4(ha);
        store_split(&sm[O_X], m, c, ha);
    }
    *(float4*)&sm[O_W3 + wk * ST + wc] = pre;
    __syncthreads();   // S4

    // ---------------- h1b = gelu(LNctx @ W1b + b1[64:]) -> H; pipeline W_out->W2 ----------------
    pre = __ldg((const float4*)(W_out + wk * DM + wc));
    {
        u64 hb[4];
        float4 x4 = __ldg((const float4*)(b1 + 64 + c));
        float4 y4 = __ldg((const float4*)(b1 + 96 + c));
        hb[0] = pk2(x4.x, x4.y); hb[1] = pk2(x4.z, x4.w);
        hb[2] = pk2(y4.x, y4.y); hb[3] = pk2(y4.z, y4.w);
        gemm64(&sm[O_C + m * ST], &sm[O_W0], c, hb);
        gelu4(hb);
        store_split(&sm[O_H], m, c, hb);
    }
    *(float4*)&sm[O_W2 + wk * ST + wc] = pre;
    __syncthreads();   // S5

    // ---------------- ffn-out = h1a@W2a + h1b@W2b + b2; z = q + ffn-out -> C ----------------
    {
        u64 oa[4];
        bias_init(oa, b2, c);
        gemm64(&sm[O_X + m * ST], &sm[O_W1], c, oa);
        gemm64(&sm[O_H + m * ST], &sm[O_W3], c, oa);
        float4 q0 = *(const float4*)&sm[O_Q + m * ST + c];
        float4 q1 = *(const float4*)&sm[O_Q + m * ST + c + 32];
        float2 f0 = up2(oa[0]), f1 = up2(oa[1]), f2 = up2(oa[2]), f3 = up2(oa[3]);
        *(float4*)&sm[O_C + m * ST + c] =
            make_float4(q0.x + f0.x, q0.y + f0.y, q0.z + f1.x, q0.w + f1.y);
        *(float4*)&sm[O_C + m * ST + c + 32] =
            make_float4(q1.x + f2.x, q1.y + f2.y, q1.z + f3.x, q1.w + f3.y);
    }
    __syncthreads();   // S6

    // ---------------- out = z @ W_out + b_out ----------------
    {
        u64 ya[4];
        bias_init(ya, b_out, c);
        gemm64(&sm[O_C + m * ST], &sm[O_W2], c, ya);
        float* op = out + (size_t)bb * LH * DM + m * DM;
        float2 f0 = up2(ya[0]), f1 = up2(ya[1]), f2 = up2(ya[2]), f3 = up2(ya[3]);
        *(float4*)(op + c)      = make_float4(f0.x, f0.y, f1.x, f1.y);
        *(float4*)(op + c + 32) = make_float4(f2.x, f2.y, f3.x, f3.y);
    }
}

extern "C" void kernel_launch(void* const* d_in, const int* in_sizes, int n_in,
                              void* d_out, int out_size)
{
    const float* hla_in   = (const float*)d_in[0];
    const float* pep_in   = (const float*)d_in[1];
    const float* W_hla    = (const float*)d_in[2];
    const float* b_hla    = (const float*)d_in[3];
    const float* W_pep    = (const float*)d_in[4];
    const float* b_pep    = (const float*)d_in[5];
    const float* rel_bias = (const float*)d_in[6];
    const float* ln_g     = (const float*)d_in[7];
    const float* ln_b     = (const float*)d_in[8];
    const float* W1       = (const float*)d_in[9];
    const float* b1       = (const float*)d_in[10];
    const float* W2       = (const float*)d_in[11];
    const float* b2       = (const float*)d_in[12];
    const float* W_out    = (const float*)d_in[13];
    const float* b_out    = (const float*)d_in[14];
    float* out = (float*)d_out;

    int B = in_sizes[0] / (LH * DM);

    cudaFuncSetAttribute(h2p_kernel, cudaFuncAttributeMaxDynamicSharedMemorySize, SMEM_BYTES);
    h2p_kernel<<<B, 1024, SMEM_BYTES>>>(hla_in, pep_in, W_hla, b_hla, W_pep, b_pep,
                                        rel_bias, ln_g, ln_b, W1, b1, W2, b2,
                                        W_out, b_out, out);
}

// round 4
// speedup vs baseline: 1.7952x; 1.7952x over previous
#include <cuda_runtime.h>

#define LH 128
#define LP 32
#define DM 64
#define HID 64
#define MAXLEN 128
#define ST 68      // smem row stride (floats): conflict-free for row-strided LDS.128
#define KST 80     // kv row stride
#define HOFF 20    // kv per-head word offset (banks disjoint across heads)

typedef unsigned long long u64;

__device__ __forceinline__ u64 pk2(float lo, float hi) {
    u64 r; asm("mov.b64 %0,{%1,%2};" : "=l"(r) : "f"(lo), "f"(hi)); return r;
}
__device__ __forceinline__ void fma2(u64& d, u64 a, u64 b) {
    asm("fma.rn.f32x2 %0,%1,%2,%3;" : "=l"(d) : "l"(a), "l"(b), "l"(d));
}
__device__ __forceinline__ void mul2(u64& d, u64 a, u64 b) {
    asm("mul.rn.f32x2 %0,%1,%2;" : "=l"(d) : "l"(a), "l"(b));
}
__device__ __forceinline__ float2 up2(u64 v) {
    float2 r; asm("mov.b64 {%0,%1},%2;" : "=f"(r.x), "=f"(r.y) : "l"(v)); return r;
}

// smem layout (floats): 24320 floats = 97280 B  -> 2 CTAs/SM
#define O_X  0                  // [64][ST] hla -> h1a -> z
#define O_C  (64*ST)            // [64][ST] pep(rows0-31) -> LN(ctx) -> h1b
#define O_Q  (2*64*ST)          // [64][ST] q
#define O_KV (3*64*ST)          // [32][KST]
#define O_PA (O_KV + LP*KST)    // weight panel A [64][ST]
#define O_PB (O_PA + 64*ST)     // weight panel B [64][ST]
#define SMEM_FLOATS (O_PB + 64*ST)
#define SMEM_BYTES  (SMEM_FLOATS * 4)

// each thread owns 4 float4 slots of a 64x64 panel: idx = i*256+t
__device__ __forceinline__ void ldg_panel(float4 pre[4], const float* __restrict__ g,
                                          int rowlen, int t) {
    #pragma unroll
    for (int i = 0; i < 4; i++) {
        int idx = i * 256 + t;
        int k = idx >> 4, c = (idx & 15) * 4;
        pre[i] = __ldg((const float4*)(g + k * rowlen + c));
    }
}
__device__ __forceinline__ void sts_panel(float* p, const float4 pre[4], int t) {
    #pragma unroll
    for (int i = 0; i < 4; i++) {
        int idx = i * 256 + t;
        int k = idx >> 4, c = (idx & 15) * 4;
        *(float4*)&p[k * ST + c] = pre[i];
    }
}

// bias for 8 contiguous cols cw..cw+7
__device__ __forceinline__ void bias8(u64 a[4], const float* __restrict__ b, int cw) {
    float4 x = __ldg((const float4*)(b + cw));
    float4 y = __ldg((const float4*)(b + cw + 4));
    a[0] = pk2(x.x, x.y); a[1] = pk2(x.z, x.w);
    a[2] = pk2(y.x, y.y); a[3] = pk2(y.z, y.w);
}

__device__ __forceinline__ void gelu4(u64 a[4]) {
    #pragma unroll
    for (int i = 0; i < 4; i++) {
        float2 f = up2(a[i]);
        f.x *= normcdff(f.x);
        f.y *= normcdff(f.y);
        a[i] = pk2(f.x, f.y);
    }
}

// acc[r][0..3] += A[l + 32r][0..63] * W[0..63][cw..cw+7]
// A row-major stride ST; W k-major stride ST; all lanes of a warp share cw -> W LDS broadcast.
template<int R>
__device__ __forceinline__ void gemmB(const float* __restrict__ sA, int l,
                                      const float* __restrict__ sW, int cw,
                                      u64 acc[][4]) {
    #pragma unroll 4
    for (int k0 = 0; k0 < 64; k0 += 4) {
        float4 a[R];
        #pragma unroll
        for (int r = 0; r < R; r++)
            a[r] = *(const float4*)&sA[(l + r * 32) * ST + k0];
        #pragma unroll
        for (int j = 0; j < 4; j++) {
            const float* wr = &sW[(k0 + j) * ST + cw];
            ulonglong2 w0 = *(const ulonglong2*)wr;        // cols cw..cw+3
            ulonglong2 w1 = *(const ulonglong2*)(wr + 4);  // cols cw+4..cw+7
            #pragma unroll
            for (int r = 0; r < R; r++) {
                float av = (j == 0) ? a[r].x : (j == 1) ? a[r].y
                         : (j == 2) ? a[r].z : a[r].w;
                u64 d = pk2(av, av);
                fma2(acc[r][0], d, w0.x);
                fma2(acc[r][1], d, w0.y);
                fma2(acc[r][2], d, w1.x);
                fma2(acc[r][3], d, w1.y);
            }
        }
    }
}

// store 2x8 tile rows l, l+32 at cols cw..cw+7
__device__ __forceinline__ void store_tile(float* dst, int l, int cw, const u64 a[][4]) {
    #pragma unroll
    for (int r = 0; r < 2; r++) {
        float2 f0 = up2(a[r][0]), f1 = up2(a[r][1]);
        float2 f2 = up2(a[r][2]), f3 = up2(a[r][3]);
        float* p = dst + (l + r * 32) * ST + cw;
        *(float4*)p       = make_float4(f0.x, f0.y, f1.x, f1.y);
        *(float4*)(p + 4) = make_float4(f2.x, f2.y, f3.x, f3.y);
    }
}

__global__ __launch_bounds__(256, 2)
void h2p_kernel(const float* __restrict__ hla_in,
                const float* __restrict__ pep_in,
                const float* __restrict__ W_hla, const float* __restrict__ b_hla,
                const float* __restrict__ W_pep, const float* __restrict__ b_pep,
                const float* __restrict__ rel_bias,
                const float* __restrict__ ln_g, const float* __restrict__ ln_b,
                const float* __restrict__ W1, const float* __restrict__ b1,
                const float* __restrict__ W2, const float* __restrict__ b2,
                const float* __restrict__ W_out, const float* __restrict__ b_out,
                float* __restrict__ out)
{
    extern __shared__ float sm[];
    const int t     = threadIdx.x;
    const int bb    = blockIdx.x;
    const int batch = bb >> 1;
    const int row0  = (bb & 1) * 64;     // this CTA covers query rows row0..row0+63
    const int w  = t >> 5;               // warp id 0..7 -> col-group
    const int l  = t & 31;               // lane -> base row
    const int cw = w * 8;                // cols cw..cw+7

    // ---------------- stage inputs + first two panels ----------------
    {
        const float4* hg = (const float4*)(hla_in + (size_t)batch * LH * DM);
        #pragma unroll
        for (int i = 0; i < 4; i++) {
            int idx = i * 256 + t;
            int r = idx >> 4, c4 = idx & 15;
            *(float4*)&sm[O_X + r * ST + c4 * 4] = hg[(row0 + r) * 16 + c4];
        }
        const float4* pg = (const float4*)(pep_in + (size_t)batch * LP * DM);
        #pragma unroll
        for (int i = 0; i < 2; i++) {
            int idx = i * 256 + t;
            int r = idx >> 4, c4 = idx & 15;
            *(float4*)&sm[O_C + r * ST + c4 * 4] = pg[idx];
        }
    }
    float4 rA[4], rB[4];
    ldg_panel(rA, W_pep, HID, t); sts_panel(&sm[O_PA], rA, t);
    ldg_panel(rB, W_hla, HID, t); sts_panel(&sm[O_PB], rB, t);
    __syncthreads();   // S0

    // ---------------- P1: kv = pep @ W_pep + b_pep -> KV ----------------
    ldg_panel(rA, W1, 2 * HID, t);               // W1 cols 0..63
    {
        u64 a4[1][4];
        bias8(a4[0], b_pep, cw);
        gemmB<1>(&sm[O_C], l, &sm[O_PA], cw, a4);
        float2 f0 = up2(a4[0][0]), f1 = up2(a4[0][1]);
        float2 f2 = up2(a4[0][2]), f3 = up2(a4[0][3]);
        float* kd = &sm[O_KV + l * KST + (cw >> 4) * HOFF + (cw & 15)];
        *(float4*)kd       = make_float4(f0.x, f0.y, f1.x, f1.y);
        *(float4*)(kd + 4) = make_float4(f2.x, f2.y, f3.x, f3.y);
    }
    __syncthreads();   // S1

    // ---------------- P2: q = hla @ W_hla + b_hla -> Q ----------------
    sts_panel(&sm[O_PA], rA, t);                 // PA := W1a   (W_pep dead)
    ldg_panel(rB, W1 + HID, 2 * HID, t);         // W1 cols 64..127
    {
        u64 qa[2][4];
        bias8(qa[0], b_hla, cw);
        qa[1][0] = qa[0][0]; qa[1][1] = qa[0][1]; qa[1][2] = qa[0][2]; qa[1][3] = qa[0][3];
        gemmB<2>(&sm[O_X], l, &sm[O_PB], cw, qa);
        store_tile(&sm[O_Q], l, cw, qa);
    }
    __syncthreads();   // S2

    // ---------------- P3: attention + LN -> C ----------------
    sts_panel(&sm[O_PB], rB, t);                 // PB := W1b   (W_hla dead)
    ldg_panel(rA, W2, HID, t);                   // W2 rows 0..63
    {
        const int r = t >> 2, h = t & 3;
        const float* qrow = &sm[O_Q + r * ST + h * 16];
        ulonglong2 qA = *(const ulonglong2*)(qrow + 0);
        ulonglong2 qB = *(const ulonglong2*)(qrow + 4);
        ulonglong2 qC = *(const ulonglong2*)(qrow + 8);
        ulonglong2 qD = *(const ulonglong2*)(qrow + 12);

        float sc[32];
        const float* brow = rel_bias + h * (MAXLEN * MAXLEN) + (row0 + r) * MAXLEN;
        #pragma unroll
        for (int k4 = 0; k4 < 8; k4++) {
            float4 bv = __ldg((const float4*)&brow[k4 * 4]);
            sc[k4*4+0] = bv.x; sc[k4*4+1] = bv.y; sc[k4*4+2] = bv.z; sc[k4*4+3] = bv.w;
        }
        #pragma unroll
        for (int k = 0; k < LP; k++) {
            const float* kr = &sm[O_KV + k * KST + h * HOFF];
            ulonglong2 v0 = *(const ulonglong2*)(kr + 0);
            ulonglong2 v1 = *(const ulonglong2*)(kr + 4);
            ulonglong2 v2 = *(const ulonglong2*)(kr + 8);
            ulonglong2 v3 = *(const ulonglong2*)(kr + 12);
            u64 s;
            mul2(s, qA.x, v0.x);
            fma2(s, qA.y, v0.y);
            fma2(s, qB.x, v1.x);
            fma2(s, qB.y, v1.y);
            fma2(s, qC.x, v2.x);
            fma2(s, qC.y, v2.y);
            fma2(s, qD.x, v3.x);
            fma2(s, qD.y, v3.y);
            float2 sp = up2(s);
            sc[k] = fmaf(0.25f, sp.x + sp.y, sc[k]);
        }
        float mx = sc[0];
        #pragma unroll
        for (int k = 1; k < LP; k++) mx = fmaxf(mx, sc[k]);
        float ssum = 0.f;
        #pragma unroll
        for (int k = 0; k < LP; k++) { sc[k] = __expf(sc[k] - mx); ssum += sc[k]; }
        float inv = 1.0f / ssum;

        u64 cx[8];
        #pragma unroll
        for (int i = 0; i < 8; i++) cx[i] = 0ull;
        #pragma unroll
        for (int k = 0; k < LP; k++) {
            const float* kr = &sm[O_KV + k * KST + h * HOFF];
            ulonglong2 v0 = *(const ulonglong2*)(kr + 0);
            ulonglong2 v1 = *(const ulonglong2*)(kr + 4);
            ulonglong2 v2 = *(const ulonglong2*)(kr + 8);
            ulonglong2 v3 = *(const ulonglong2*)(kr + 12);
            u64 pd = pk2(sc[k], sc[k]);
            fma2(cx[0], pd, v0.x); fma2(cx[1], pd, v0.y);
            fma2(cx[2], pd, v1.x); fma2(cx[3], pd, v1.y);
            fma2(cx[4], pd, v2.x); fma2(cx[5], pd, v2.y);
            fma2(cx[6], pd, v3.x); fma2(cx[7], pd, v3.y);
        }
        float x[16];
        #pragma unroll
        for (int i = 0; i < 8; i++) {
            float2 f = up2(cx[i]);
            x[2*i]   = f.x * inv;
            x[2*i+1] = f.y * inv;
        }
        float s1 = 0.f, s2 = 0.f;
        #pragma unroll
        for (int i = 0; i < 16; i++) { s1 += x[i]; s2 = fmaf(x[i], x[i], s2); }
        s1 += __shfl_xor_sync(0xffffffffu, s1, 1);
        s2 += __shfl_xor_sync(0xffffffffu, s2, 1);
        s1 += __shfl_xor_sync(0xffffffffu, s1, 2);
        s2 += __shfl_xor_sync(0xffffffffu, s2, 2);
        float mu   = s1 * (1.0f / 64.0f);
        float var  = s2 * (1.0f / 64.0f) - mu * mu;
        float rstd = rsqrtf(var + 1e-5f);
        #pragma unroll
        for (int c4 = 0; c4 < 4; c4++) {
            float4 gv = __ldg((const float4*)&ln_g[h * 16 + c4 * 4]);
            float4 bv = __ldg((const float4*)&ln_b[h * 16 + c4 * 4]);
            float4 o;
            o.x = (x[c4*4+0] - mu) * rstd * gv.x + bv.x;
            o.y = (x[c4*4+1] - mu) * rstd * gv.y + bv.y;
            o.z = (x[c4*4+2] - mu) * rstd * gv.z + bv.z;
            o.w = (x[c4*4+3] - mu) * rstd * gv.w + bv.w;
            *(float4*)&sm[O_C + r * ST + h * 16 + c4 * 4] = o;
        }
    }
    __syncthreads();   // S3

    // ---------------- P4: h1a = gelu(C @ W1a + b1a) -> X ----------------
    ldg_panel(rB, W2 + HID * HID, HID, t);       // W2 rows 64..127
    {
        u64 ha[2][4];
        bias8(ha[0], b1, cw);
        ha[1][0] = ha[0][0]; ha[1][1] = ha[0][1]; ha[1][2] = ha[0][2]; ha[1][3] = ha[0][3];
        gemmB<2>(&sm[O_C], l, &sm[O_PA], cw, ha);
        gelu4(ha[0]); gelu4(ha[1]);
        store_tile(&sm[O_X], l, cw, ha);
    }
    __syncthreads();   // S4

    // ---------------- P5: h1b = gelu(C @ W1b + b1b) -> regs ----------------
    sts_panel(&sm[O_PA], rA, t);                 // PA := W2a  (W1a dead)
    u64 hb[2][4];
    bias8(hb[0], b1 + HID, cw);
    hb[1][0] = hb[0][0]; hb[1][1] = hb[0][1]; hb[1][2] = hb[0][2]; hb[1][3] = hb[0][3];
    gemmB<2>(&sm[O_C], l, &sm[O_PB], cw, hb);
    gelu4(hb[0]); gelu4(hb[1]);
    __syncthreads();   // S5

    // ---------------- P6: h1b -> C ; oacc = b2 + h1a @ W2a ----------------
    store_tile(&sm[O_C], l, cw, hb);             // C := h1b (LNctx dead)
    sts_panel(&sm[O_PB], rB, t);                 // PB := W2b (W1b dead)
    ldg_panel(rA, W_out, DM, t);
    u64 oacc[2][4];
    bias8(oacc[0], b2, cw);
    oacc[1][0] = oacc[0][0]; oacc[1][1] = oacc[0][1];
    oacc[1][2] = oacc[0][2]; oacc[1][3] = oacc[0][3];
    gemmB<2>(&sm[O_X], l, &sm[O_PA], cw, oacc);
    __syncthreads();   // S6

    // ---------------- P7: oacc += h1b @ W2b ; z = q + oacc -> X ----------------
    gemmB<2>(&sm[O_C], l, &sm[O_PB], cw, oacc);
    #pragma unroll
    for (int r = 0; r < 2; r++) {
        const float* qp = &sm[O_Q + (l + r * 32) * ST + cw];
        float4 q0 = *(const float4*)qp;
        float4 q1 = *(const float4*)(qp + 4);
        float2 f0 = up2(oacc[r][0]), f1 = up2(oacc[r][1]);
        float2 f2 = up2(oacc[r][2]), f3 = up2(oacc[r][3]);
        float* xp = &sm[O_X + (l + r * 32) * ST + cw];
        *(float4*)xp       = make_float4(q0.x + f0.x, q0.y + f0.y, q0.z + f1.x, q0.w + f1.y);
        *(float4*)(xp + 4) = make_float4(q1.x + f2.x, q1.y + f2.y, q1.z + f3.x, q1.w + f3.y);
    }
    sts_panel(&sm[O_PA], rA, t);                 // PA := W_out (W2a dead)
    __syncthreads();   // S7

    // ---------------- P8: out = z @ W_out + b_out ----------------
    {
        u64 ya[2][4];
        bias8(ya[0], b_out, cw);
        ya[1][0] = ya[0][0]; ya[1][1] = ya[0][1]; ya[1][2] = ya[0][2]; ya[1][3] = ya[0][3];
        gemmB<2>(&sm[O_X], l, &sm[O_PA], cw, ya);
        float* ob = out + (size_t)batch * LH * DM;
        #pragma unroll
        for (int r = 0; r < 2; r++) {
            float2 f0 = up2(ya[r][0]), f1 = up2(ya[r][1]);
            float2 f2 = up2(ya[r][2]), f3 = up2(ya[r][3]);
            float* op = ob + (row0 + l + r * 32) * DM + cw;
            *(float4*)op       = make_float4(f0.x, f0.y, f1.x, f1.y);
            *(float4*)(op + 4) = make_float4(f2.x, f2.y, f3.x, f3.y);
        }
    }
}

extern "C" void kernel_launch(void* const* d_in, const int* in_sizes, int n_in,
                              void* d_out, int out_size)
{
    const float* hla_in   = (const float*)d_in[0];
    const float* pep_in   = (const float*)d_in[1];
    const float* W_hla    = (const float*)d_in[2];
    const float* b_hla    = (const float*)d_in[3];
    const float* W_pep    = (const float*)d_in[4];
    const float* b_pep    = (const float*)d_in[5];
    const float* rel_bias = (const float*)d_in[6];
    const float* ln_g     = (const float*)d_in[7];
    const float* ln_b     = (const float*)d_in[8];
    const float* W1       = (const float*)d_in[9];
    const float* b1       = (const float*)d_in[10];
    const float* W2       = (const float*)d_in[11];
    const float* b2       = (const float*)d_in[12];
    const float* W_out    = (const float*)d_in[13];
    const float* b_out    = (const float*)d_in[14];
    float* out = (float*)d_out;

    int B = in_sizes[0] / (LH * DM);

    cudaFuncSetAttribute(h2p_kernel, cudaFuncAttributeMaxDynamicSharedMemorySize, SMEM_BYTES);
    h2p_kernel<<<2 * B, 256, SMEM_BYTES>>>(hla_in, pep_in, W_hla, b_hla, W_pep, b_pep,
                                           rel_bias, ln_g, ln_b, W1, b1, W2, b2,
                                           W_out, b_out, out);
}